// round 7
// baseline (speedup 1.0000x reference)
#include <cuda_runtime.h>
#include <cstdint>
#include <math.h>

#define NTHREADS 512
#define TM 64
#define SSTR 132   /* state / h / refined row stride  (132 % 32 == 4) */
#define ASTR 260   /* activation row stride           (260 % 32 == 4) */

#define SH_OFF   (TM * SSTR)              /* 8448  */
#define SACT_OFF (SH_OFF + TM * SSTR)     /* 16896 */
#define SW_OFF   (SACT_OFF + TM * ASTR)   /* 33536 */
#define SW_TILE  4096
#define SMEM_FLOATS (SW_OFF + 2 * SW_TILE) /* 41728 */
#define SMEM_BYTES  (SMEM_FLOATS * 4)      /* 166912 B */

typedef unsigned long long u64;

// k-pair-interleaved weights (constant across run; packed once per launch)
__device__ float W1P[128 * 256];
__device__ float W2P[256 * 128];
__device__ float WGP[256 * 128];

// ---------------- packed f32x2 (Blackwell FFMA2) ----------------
__device__ __forceinline__ u64 fma2(u64 a, u64 b, u64 c) {
    u64 d;
    asm("fma.rn.f32x2 %0, %1, %2, %3;" : "=l"(d) : "l"(a), "l"(b), "l"(c));
    return d;
}
__device__ __forceinline__ float2 unpack2(u64 v) {
    float lo, hi;
    asm("mov.b64 {%0, %1}, %2;" : "=f"(lo), "=f"(hi) : "l"(v));
    return make_float2(lo, hi);
}

// ---------------- cp.async ----------------
__device__ __forceinline__ void cp_async16(unsigned saddr, const void* g) {
    asm volatile("cp.async.ca.shared.global [%0], [%1], 16;" ::"r"(saddr), "l"(g));
}
__device__ __forceinline__ void cp_commit() {
    asm volatile("cp.async.commit_group;" ::: "memory");
}
__device__ __forceinline__ void cp_wait0() {
    asm volatile("cp.async.wait_group 0;" ::: "memory");
}
// one 4096-float (16KB) weight tile: 512 threads x 2 float4
__device__ __forceinline__ void prefetch_tile(float* sdst, const float* g) {
    unsigned s = (unsigned)__cvta_generic_to_shared(sdst);
    const float4* g4 = (const float4*)g;
    int tid = threadIdx.x;
    cp_async16(s + tid * 16, g4 + tid);
    cp_async16(s + (tid + 512) * 16, g4 + tid + 512);
    cp_commit();
}

__device__ __forceinline__ float gelu_f(float x) {
    return 0.5f * x * (1.0f + erff(x * 0.7071067811865476f));
}

// ---------------- weight pre-pack: out[kp][n] = (in[2kp][n], in[2kp+1][n]) ----
__global__ void pack_weights_kernel(const float* __restrict__ w1,
                                    const float* __restrict__ w2,
                                    const float* __restrict__ wg) {
    int i = blockIdx.x * blockDim.x + threadIdx.x;  // 0 .. 49151
    int m = i >> 14;
    int r = i & 16383;
    if (m == 0) {
        int kp = r >> 8, n = r & 255;
        ((float2*)W1P)[r] = make_float2(w1[(2 * kp) * 256 + n], w1[(2 * kp + 1) * 256 + n]);
    } else if (m == 1) {
        int kp = r >> 7, n = r & 127;
        ((float2*)W2P)[r] = make_float2(w2[(2 * kp) * 128 + n], w2[(2 * kp + 1) * 128 + n]);
    } else {
        int kp = r >> 7, n = r & 127;
        ((float2*)WGP)[r] = make_float2(wg[(2 * kp) * 128 + n], wg[(2 * kp + 1) * 128 + n]);
    }
}

// ---------------- k-paired GEMM segment ----------------
// C[64 x N] += A[64 x K] * B[K x N].  A in SMEM (row-major, stride ASTRv),
// B pre-paired in global, streamed through 2x16KB SMEM tiles.
// NU   = u64 columns per kp-row (= N)
// NPQ  = q-groups per thread (thread owns 2*NPQ float cols)
// acc[rr*2*NPQ + q*2 + j]: u64 = (even-k partial, odd-k partial) of
//   C[row0 + rr*4][colbase + q*16 + 2*lx + j]
template <int NU, int NPQ, int ASTRv>
__device__ __forceinline__ void gemm_p(const float* __restrict__ Arow,
                                       const float* __restrict__ Bg, int ntiles,
                                       float* sW, u64* acc, int ucol0) {
    constexpr int KPT = 2048 / NU;  // kp rows per tile (8 for NU=256, 16 for NU=128)
    prefetch_tile(sW, Bg);
    cp_wait0();
    __syncthreads();
    for (int t = 0; t < ntiles; t++) {
        if (t + 1 < ntiles) prefetch_tile(sW + ((t + 1) & 1) * SW_TILE, Bg + (t + 1) * SW_TILE);
        const u64* sB = (const u64*)(sW + (t & 1) * SW_TILE);
        const float* At = Arow + t * (KPT * 2);
#pragma unroll
        for (int kq = 0; kq < KPT / 2; kq++) {
            ulonglong2 a[4];
#pragma unroll
            for (int rr = 0; rr < 4; rr++)
                a[rr] = *(const ulonglong2*)(At + rr * 4 * ASTRv + kq * 4);
#pragma unroll
            for (int j = 0; j < 2; j++) {
                const u64* bp = sB + (kq * 2 + j) * NU + ucol0;
                u64 b[2 * NPQ];
#pragma unroll
                for (int q = 0; q < NPQ; q++)
                    *(ulonglong2*)&b[2 * q] = *(const ulonglong2*)(bp + q * 16);
#pragma unroll
                for (int rr = 0; rr < 4; rr++) {
                    u64 av = j ? a[rr].y : a[rr].x;
#pragma unroll
                    for (int c = 0; c < 2 * NPQ; c++)
                        acc[rr * 2 * NPQ + c] = fma2(av, b[c], acc[rr * 2 * NPQ + c]);
                }
            }
        }
        cp_wait0();
        __syncthreads();
    }
}

// ---------------- main fused recurrent kernel ----------------
__global__ void __launch_bounds__(NTHREADS, 1)
TinyRecurrentWorkshop_69054484185493_kernel(
    const float* __restrict__ x,
    const float* __restrict__ ln_w, const float* __restrict__ ln_b,
    const float* __restrict__ b1, const float* __restrict__ b2,
    const float* __restrict__ bg,
    const int* __restrict__ passes_p,
    float* __restrict__ out) {
    extern __shared__ float smem[];
    float* sS = smem;              // state   64 x 132
    float* sH = smem + SH_OFF;     // h, then refined  64 x 132
    float* sA = smem + SACT_OFF;   // gelu activations 64 x 260
    float* sW = smem + SW_OFF;     // weight tiles 2 x 4096

    const int tid = threadIdx.x;
    const int w = tid >> 5, lane = tid & 31;
    const int wr = w >> 2, wc = w & 3;
    const int ly = lane >> 3, lx = lane & 7;
    const int row0 = wr * 16 + ly;          // + rr*4 for rr = 0..3
    const int uc1 = wc * 64 + lx * 2;       // M1 u64-col base (N=256)
    const int uc2 = wc * 32 + lx * 2;       // M2/M3 (N=128)
    const int cb1 = wc * 64 + lx * 2;       // float col bases (same as u64 index)
    const int cb2 = wc * 32 + lx * 2;
    const long long rowBase = (long long)blockIdx.x * TM;

    // ---- load state tile: 64x128 = 2048 float4 ----
    {
        const float4* xg = (const float4*)(x + rowBase * 128);
#pragma unroll
        for (int i = 0; i < 4; i++) {
            int idx = tid + i * NTHREADS;
            *(float4*)&sS[(idx >> 5) * SSTR + (idx & 31) * 4] = xg[idx];
        }
    }

    int npass = passes_p[0];
    if (npass < 1 || npass > 1024) {
        float f = __int_as_float(npass);
        npass = (int)f;
        if (npass < 1 || npass > 1024) npass = 8;
    }
    __syncthreads();

    const int lrow = tid >> 3;  // 8 threads / row for LN
    const int lq = tid & 7;

    for (int pass = 0; pass < npass; pass++) {
        // ---------- LayerNorm: sS -> sH ----------
        {
            float4 xv[4];
            const float* sr = sS + lrow * SSTR + lq * 16;
            float s = 0.f;
#pragma unroll
            for (int j = 0; j < 4; j++) {
                xv[j] = *(const float4*)(sr + j * 4);
                s += (xv[j].x + xv[j].y) + (xv[j].z + xv[j].w);
            }
            s += __shfl_xor_sync(0xFFFFFFFFu, s, 1);
            s += __shfl_xor_sync(0xFFFFFFFFu, s, 2);
            s += __shfl_xor_sync(0xFFFFFFFFu, s, 4);
            const float mu = s * (1.0f / 128.0f);
            float q = 0.f;
#pragma unroll
            for (int j = 0; j < 4; j++) {
                float d0 = xv[j].x - mu, d1 = xv[j].y - mu;
                float d2 = xv[j].z - mu, d3 = xv[j].w - mu;
                q += d0 * d0 + d1 * d1 + d2 * d2 + d3 * d3;
            }
            q += __shfl_xor_sync(0xFFFFFFFFu, q, 1);
            q += __shfl_xor_sync(0xFFFFFFFFu, q, 2);
            q += __shfl_xor_sync(0xFFFFFFFFu, q, 4);
            const float rstd = rsqrtf(q * (1.0f / 128.0f) + 1e-5f);
            float* hr = sH + lrow * SSTR + lq * 16;
#pragma unroll
            for (int j = 0; j < 4; j++) {
                float4 wv = __ldg((const float4*)ln_w + lq * 4 + j);
                float4 bv = __ldg((const float4*)ln_b + lq * 4 + j);
                float4 h;
                h.x = (xv[j].x - mu) * rstd * wv.x + bv.x;
                h.y = (xv[j].y - mu) * rstd * wv.y + bv.y;
                h.z = (xv[j].z - mu) * rstd * wv.z + bv.z;
                h.w = (xv[j].w - mu) * rstd * wv.w + bv.w;
                *(float4*)(hr + j * 4) = h;
            }
        }
        // (ordering: gemm_p's internal barrier precedes any sH read)

        // ---------- M1: g = h @ w1  (64x256, K=128) ----------
        u64 acc1[32];
#pragma unroll
        for (int i = 0; i < 32; i++) acc1[i] = 0ULL;
        gemm_p<256, 4, SSTR>(sH + row0 * SSTR, W1P, 8, sW, acc1, uc1);

        // gelu(g + b1) -> sA
        {
            float2 bb[4];
#pragma unroll
            for (int q = 0; q < 4; q++)
                bb[q] = __ldg((const float2*)(b1 + cb1 + q * 16));
#pragma unroll
            for (int rr = 0; rr < 4; rr++) {
                float* ar = sA + (row0 + rr * 4) * ASTR + cb1;
#pragma unroll
                for (int q = 0; q < 4; q++) {
                    float2 u0 = unpack2(acc1[rr * 8 + q * 2 + 0]);
                    float2 u1 = unpack2(acc1[rr * 8 + q * 2 + 1]);
                    float2 o;
                    o.x = gelu_f(u0.x + u0.y + bb[q].x);
                    o.y = gelu_f(u1.x + u1.y + bb[q].y);
                    *(float2*)(ar + q * 16) = o;
                }
            }
        }

        // ---------- M2: refined = act @ w2 + b2  (64x128, K=256) ----------
        u64 acc2[16];
#pragma unroll
        for (int i = 0; i < 16; i++) acc2[i] = 0ULL;
        gemm_p<128, 2, ASTR>(sA + row0 * ASTR, W2P, 8, sW, acc2, uc2);

        float rf[16];
        {
            float2 bb[2];
#pragma unroll
            for (int q = 0; q < 2; q++)
                bb[q] = __ldg((const float2*)(b2 + cb2 + q * 16));
#pragma unroll
            for (int rr = 0; rr < 4; rr++) {
                float* hr = sH + (row0 + rr * 4) * SSTR + cb2;
#pragma unroll
                for (int q = 0; q < 2; q++) {
                    float2 u0 = unpack2(acc2[rr * 4 + q * 2 + 0]);
                    float2 u1 = unpack2(acc2[rr * 4 + q * 2 + 1]);
                    float v0 = u0.x + u0.y + bb[q].x;
                    float v1 = u1.x + u1.y + bb[q].y;
                    rf[rr * 4 + q * 2 + 0] = v0;
                    rf[rr * 4 + q * 2 + 1] = v1;
                    *(float2*)(hr + q * 16) = make_float2(v0, v1);  // refined -> sH
                }
            }
        }

        // ---------- M3: z = state @ wg_s + refined @ wg_r + bg ----------
        u64 acc3[16];
#pragma unroll
        for (int i = 0; i < 16; i++) acc3[i] = 0ULL;
        gemm_p<128, 2, SSTR>(sS + row0 * SSTR, WGP, 4, sW, acc3, uc2);
        gemm_p<128, 2, SSTR>(sH + row0 * SSTR, WGP + 4 * SW_TILE, 4, sW, acc3, uc2);

        // gate + residual update
        {
            float2 bb[2];
#pragma unroll
            for (int q = 0; q < 2; q++)
                bb[q] = __ldg((const float2*)(bg + cb2 + q * 16));
#pragma unroll
            for (int rr = 0; rr < 4; rr++) {
                float* srw = sS + (row0 + rr * 4) * SSTR + cb2;
#pragma unroll
                for (int q = 0; q < 2; q++) {
                    float2 u0 = unpack2(acc3[rr * 4 + q * 2 + 0]);
                    float2 u1 = unpack2(acc3[rr * 4 + q * 2 + 1]);
                    float z0 = u0.x + u0.y + bb[q].x;
                    float z1 = u1.x + u1.y + bb[q].y;
                    float g0 = 1.0f / (1.0f + expf(-z0));
                    float g1 = 1.0f / (1.0f + expf(-z1));
                    srw[q * 16 + 0] += g0 * rf[rr * 4 + q * 2 + 0];
                    srw[q * 16 + 1] += g1 * rf[rr * 4 + q * 2 + 1];
                }
            }
        }
        __syncthreads();  // state update visible to next pass's LN
    }

    // ---- store result ----
    {
        float4* og = (float4*)(out + rowBase * 128);
#pragma unroll
        for (int i = 0; i < 4; i++) {
            int idx = tid + i * NTHREADS;
            og[idx] = *(const float4*)&sS[(idx >> 5) * SSTR + (idx & 31) * 4];
        }
    }
}

extern "C" void kernel_launch(void* const* d_in, const int* in_sizes, int n_in,
                              void* d_out, int out_size) {
    const float* x    = (const float*)d_in[0];
    const float* ln_w = (const float*)d_in[1];
    const float* ln_b = (const float*)d_in[2];
    const float* w1   = (const float*)d_in[3];
    const float* b1   = (const float*)d_in[4];
    const float* w2   = (const float*)d_in[5];
    const float* b2   = (const float*)d_in[6];
    const float* wg   = (const float*)d_in[7];
    const float* bg   = (const float*)d_in[8];
    const int* passes = (const int*)d_in[9];
    float* out = (float*)d_out;

    // pack weights into k-pair-interleaved layout (constant; cheap)
    pack_weights_kernel<<<192, 256>>>(w1, w2, wg);

    const int nrows = in_sizes[0] / 128;
    const int blocks = nrows / TM;

    cudaFuncSetAttribute(TinyRecurrentWorkshop_69054484185493_kernel,
                         cudaFuncAttributeMaxDynamicSharedMemorySize, SMEM_BYTES);
    TinyRecurrentWorkshop_69054484185493_kernel<<<blocks, NTHREADS, SMEM_BYTES>>>(
        x, ln_w, ln_b, b1, b2, bg, passes, out);
}

// round 8
// speedup vs baseline: 1.0365x; 1.0365x over previous
#include <cuda_runtime.h>
#include <cstdint>
#include <math.h>

#define NTHREADS 256
#define TM 64
#define SSTR 132                    /* state stride (132 % 32 == 4) */
#define ASTR 260                    /* activation stride (260 % 32 == 4) */

#define SA_OFF (TM * SSTR)          /* 8448 */
#define SW_OFF (SA_OFF + TM * ASTR) /* 25088 */
#define TILE_F 2048                 /* 8KB weight tile */
#define SMEM_FLOATS (SW_OFF + 4 * TILE_F) /* 33280 */
#define SMEM_BYTES (SMEM_FLOATS * 4)      /* 133120 B */

typedef unsigned long long u64;

// k-pair-interleaved weights (constant; packed once per launch)
__device__ float W1P[128 * 256];
__device__ float W2P[256 * 128];
__device__ float WGP[256 * 128];

// ---------------- packed f32x2 (Blackwell FFMA2) ----------------
__device__ __forceinline__ u64 fma2(u64 a, u64 b, u64 c) {
    u64 d;
    asm("fma.rn.f32x2 %0, %1, %2, %3;" : "=l"(d) : "l"(a), "l"(b), "l"(c));
    return d;
}
__device__ __forceinline__ float sum2(u64 v) {
    float lo, hi;
    asm("mov.b64 {%0, %1}, %2;" : "=f"(lo), "=f"(hi) : "l"(v));
    return lo + hi;
}

// ---------------- cp.async ----------------
__device__ __forceinline__ void cp_async16(unsigned saddr, const void* g) {
    asm volatile("cp.async.ca.shared.global [%0], [%1], 16;" ::"r"(saddr), "l"(g));
}
__device__ __forceinline__ void cp_commit() {
    asm volatile("cp.async.commit_group;" ::: "memory");
}
__device__ __forceinline__ void cp_wait0() {
    asm volatile("cp.async.wait_group 0;" ::: "memory");
}

template <int NV, int NTHR>
__device__ __forceinline__ void ldtile(float* dst, const float* g, int slot) {
    unsigned s = (unsigned)__cvta_generic_to_shared(dst);
    const float4* g4 = (const float4*)g;
#pragma unroll
    for (int i = 0; i < NV; i++)
        cp_async16(s + (slot + i * NTHR) * 16, g4 + slot + i * NTHR);
    cp_commit();
}

__device__ __forceinline__ float gelu_f(float x) {
    return 0.5f * x * (1.0f + erff(x * 0.7071067811865476f));
}

// ---------------- weight pre-pack: out[kp][n] = (in[2kp][n], in[2kp+1][n]) ---
__global__ void pack_weights_kernel(const float* __restrict__ w1,
                                    const float* __restrict__ w2,
                                    const float* __restrict__ wg) {
    int i = blockIdx.x * blockDim.x + threadIdx.x;  // 0 .. 49151
    int m = i >> 14;
    int r = i & 16383;
    if (m == 0) {
        int kp = r >> 8, n = r & 255;
        ((float2*)W1P)[r] = make_float2(w1[(2 * kp) * 256 + n], w1[(2 * kp + 1) * 256 + n]);
    } else if (m == 1) {
        int kp = r >> 7, n = r & 127;
        ((float2*)W2P)[r] = make_float2(w2[(2 * kp) * 128 + n], w2[(2 * kp + 1) * 128 + n]);
    } else {
        int kp = r >> 7, n = r & 127;
        ((float2*)WGP)[r] = make_float2(wg[(2 * kp) * 128 + n], wg[(2 * kp + 1) * 128 + n]);
    }
}

// ---------------- k-paired GEMM, 8 rows x 8 u64-cols per thread -------------
// acc[rr*8 + q*2 + j] (u64) = (even,odd) k-partials of C[row0+rr][ucol + q*QS + j]
// A: SMEM, k-consecutive floats; one ulonglong2 per row covers 2 k-pairs (4 k).
// B: k-pair-packed weights in global, streamed through two 8KB SMEM buffers.
template <int NU, int KQT, int NV, int NTHR>
__device__ __forceinline__ void gemm64(const float* __restrict__ A0, int astr,
                                       const float* __restrict__ Bg, int ntiles,
                                       float* b0, float* b1, u64* acc,
                                       int ucol, int lslot) {
    constexpr int QS = NU / 4;
    ldtile<NV, NTHR>(b0, Bg, lslot);
    cp_wait0();
    __syncthreads();
    for (int t = 0; t < ntiles; t++) {
        if (t + 1 < ntiles)
            ldtile<NV, NTHR>(((t + 1) & 1) ? b1 : b0, Bg + (t + 1) * TILE_F, lslot);
        const float* sB = (t & 1) ? b1 : b0;
        const float* At = A0 + t * (KQT * 4);
#pragma unroll
        for (int kq = 0; kq < KQT; kq++) {
            ulonglong2 a[8];
#pragma unroll
            for (int rr = 0; rr < 8; rr++)
                a[rr] = *(const ulonglong2*)(At + rr * astr + kq * 4);
#pragma unroll
            for (int j = 0; j < 2; j++) {
                const u64* bp = (const u64*)sB + (kq * 2 + j) * NU + ucol;
                u64 b[8];
#pragma unroll
                for (int q = 0; q < 4; q++)
                    *(ulonglong2*)&b[2 * q] = *(const ulonglong2*)(bp + q * QS);
#pragma unroll
                for (int rr = 0; rr < 8; rr++) {
                    u64 av = j ? a[rr].y : a[rr].x;
#pragma unroll
                    for (int c = 0; c < 8; c++)
                        acc[rr * 8 + c] = fma2(av, b[c], acc[rr * 8 + c]);
                }
            }
        }
        cp_wait0();
        __syncthreads();
    }
}

// ---------------- main fused recurrent kernel ----------------
__global__ void __launch_bounds__(NTHREADS, 1)
TinyRecurrentWorkshop_69054484185493_kernel(
    const float* __restrict__ x,
    const float* __restrict__ ln_w, const float* __restrict__ ln_b,
    const float* __restrict__ b1, const float* __restrict__ b2,
    const float* __restrict__ bg,
    const int* __restrict__ passes_p,
    float* __restrict__ out) {
    extern __shared__ float smem[];
    float* sS = smem;             // state 64 x 132
    float* sA = smem + SA_OFF;    // h / act / scratch / refined : 64 x 260
    float* sW = smem + SW_OFF;    // 4 x 2048 weight tile buffers

    const int tid = threadIdx.x;
    const int w = tid >> 5, lane = tid & 31;
    // M1 map: 8 warps; warp w rows w*8..+7; lane owns u64 cols q*64 + 2*lane (+1)
    const int m1row = w * 8;
    const int m1uc = 2 * lane;
    // layered (M2/M3) map: layer = tid>>7; 4 warps/layer; rows w4*16+ly*8+rr;
    // lane half lx owns u64 cols q*32 + 2*lx (+1)
    const int layer = tid >> 7;
    const int ltid = tid & 127;
    const int w4 = ltid >> 5;
    const int ly = lane >> 4, lx = lane & 15;
    const int lrow0 = w4 * 16 + ly * 8;
    const int luc = 2 * lx;
    float* lb0 = sW + layer * 2 * TILE_F;
    float* lb1 = lb0 + TILE_F;
    const long long rowBase = (long long)blockIdx.x * TM;

    // ---- load state tile: 64x128 = 2048 float4 over 256 threads ----
    {
        const float4* xg = (const float4*)(x + rowBase * 128);
#pragma unroll
        for (int i = 0; i < 8; i++) {
            int idx = tid + i * NTHREADS;
            *(float4*)&sS[(idx >> 5) * SSTR + (idx & 31) * 4] = xg[idx];
        }
    }

    int npass = passes_p[0];
    if (npass < 1 || npass > 1024) {
        float f = __int_as_float(npass);
        npass = (int)f;
        if (npass < 1 || npass > 1024) npass = 8;
    }
    __syncthreads();

    const int lrow = tid >> 2;  // 4 threads / row for LN
    const int lq = tid & 3;

    for (int pass = 0; pass < npass; pass++) {
        // ---------- LayerNorm: sS -> h in sA[:, 0:128] ----------
        {
            float4 xv[8];
            const float* sr = sS + lrow * SSTR + lq * 32;
            float s = 0.f;
#pragma unroll
            for (int j = 0; j < 8; j++) {
                xv[j] = *(const float4*)(sr + j * 4);
                s += (xv[j].x + xv[j].y) + (xv[j].z + xv[j].w);
            }
            s += __shfl_xor_sync(0xFFFFFFFFu, s, 1);
            s += __shfl_xor_sync(0xFFFFFFFFu, s, 2);
            const float mu = s * (1.0f / 128.0f);
            float q = 0.f;
#pragma unroll
            for (int j = 0; j < 8; j++) {
                float d0 = xv[j].x - mu, d1 = xv[j].y - mu;
                float d2 = xv[j].z - mu, d3 = xv[j].w - mu;
                q += d0 * d0 + d1 * d1 + d2 * d2 + d3 * d3;
            }
            q += __shfl_xor_sync(0xFFFFFFFFu, q, 1);
            q += __shfl_xor_sync(0xFFFFFFFFu, q, 2);
            const float rstd = rsqrtf(q * (1.0f / 128.0f) + 1e-5f);
            float* hr = sA + lrow * ASTR + lq * 32;
#pragma unroll
            for (int j = 0; j < 8; j++) {
                float4 wv = __ldg((const float4*)ln_w + lq * 8 + j);
                float4 bv = __ldg((const float4*)ln_b + lq * 8 + j);
                float4 h;
                h.x = (xv[j].x - mu) * rstd * wv.x + bv.x;
                h.y = (xv[j].y - mu) * rstd * wv.y + bv.y;
                h.z = (xv[j].z - mu) * rstd * wv.z + bv.z;
                h.w = (xv[j].w - mu) * rstd * wv.w + bv.w;
                *(float4*)(hr + j * 4) = h;
            }
        }
        // gemm64's initial internal sync orders h-writes before A-reads.

        u64 acc[64];

        // ---------- M1: g = h @ w1 (64x256, K=128), all 8 warps ----------
#pragma unroll
        for (int i = 0; i < 64; i++) acc[i] = 0ULL;
        gemm64<256, 2, 2, 256>(sA + m1row * ASTR, ASTR, W1P, 16,
                               sW, sW + TILE_F, acc, m1uc, tid);
        // gelu(g + b1) -> sA[:, 0:256] (overwrites h; safe post-sync)
        {
#pragma unroll
            for (int rr = 0; rr < 8; rr++) {
                float* ar = sA + (m1row + rr) * ASTR;
#pragma unroll
                for (int q = 0; q < 4; q++) {
                    int c0 = q * 64 + 2 * lane;
                    float2 bb = __ldg((const float2*)(b1 + c0));
                    float2 o;
                    o.x = gelu_f(sum2(acc[rr * 8 + q * 2 + 0]) + bb.x);
                    o.y = gelu_f(sum2(acc[rr * 8 + q * 2 + 1]) + bb.y);
                    *(float2*)(ar + c0) = o;
                }
            }
        }

        // ---------- M2: refined = act @ w2 + b2 (64x128, K=256), 2-way k-split
#pragma unroll
        for (int i = 0; i < 64; i++) acc[i] = 0ULL;
        gemm64<128, 4, 4, 128>(sA + lrow0 * ASTR + layer * 128, ASTR,
                               W2P + layer * 16384, 8, lb0, lb1, acc, luc, ltid);
        if (layer == 1) {  // write k-half partials to scratch sA[:, 0:128]
#pragma unroll
            for (int rr = 0; rr < 8; rr++) {
                float* sc = sA + (lrow0 + rr) * ASTR;
#pragma unroll
                for (int q = 0; q < 4; q++) {
                    float2 v;
                    v.x = sum2(acc[rr * 8 + q * 2 + 0]);
                    v.y = sum2(acc[rr * 8 + q * 2 + 1]);
                    *(float2*)(sc + q * 32 + 2 * lx) = v;
                }
            }
        }
        __syncthreads();
        if (layer == 0) {  // reduce + bias -> refined in sA[:, 128:256]
#pragma unroll
            for (int rr = 0; rr < 8; rr++) {
                float* row = sA + (lrow0 + rr) * ASTR;
#pragma unroll
                for (int q = 0; q < 4; q++) {
                    int c0 = q * 32 + 2 * lx;
                    float2 sc = *(const float2*)(row + c0);
                    float2 bb = __ldg((const float2*)(b2 + c0));
                    float2 v;
                    v.x = sum2(acc[rr * 8 + q * 2 + 0]) + sc.x + bb.x;
                    v.y = sum2(acc[rr * 8 + q * 2 + 1]) + sc.y + bb.y;
                    *(float2*)(row + 128 + c0) = v;
                }
            }
        }

        // ---------- M3: z = state @ wg_s + refined @ wg_r + bg --------------
        // layer 0: state half; layer 1: refined half (natural k-split)
#pragma unroll
        for (int i = 0; i < 64; i++) acc[i] = 0ULL;
        {
            const float* A3 = layer ? (sA + lrow0 * ASTR + 128)
                                    : (sS + lrow0 * SSTR);
            const int astr3 = layer ? ASTR : SSTR;
            gemm64<128, 4, 4, 128>(A3, astr3, WGP + layer * 16384, 8,
                                   lb0, lb1, acc, luc, ltid);
        }
        if (layer == 1) {  // refined-half partials -> scratch sA[:, 0:128]
#pragma unroll
            for (int rr = 0; rr < 8; rr++) {
                float* sc = sA + (lrow0 + rr) * ASTR;
#pragma unroll
                for (int q = 0; q < 4; q++) {
                    float2 v;
                    v.x = sum2(acc[rr * 8 + q * 2 + 0]);
                    v.y = sum2(acc[rr * 8 + q * 2 + 1]);
                    *(float2*)(sc + q * 32 + 2 * lx) = v;
                }
            }
        }
        __syncthreads();
        if (layer == 0) {  // gate + residual update
#pragma unroll
            for (int rr = 0; rr < 8; rr++) {
                float* row = sA + (lrow0 + rr) * ASTR;
                float* srw = sS + (lrow0 + rr) * SSTR;
#pragma unroll
                for (int q = 0; q < 4; q++) {
                    int c0 = q * 32 + 2 * lx;
                    float2 sc = *(const float2*)(row + c0);
                    float2 bb = __ldg((const float2*)(bg + c0));
                    float z0 = sum2(acc[rr * 8 + q * 2 + 0]) + sc.x + bb.x;
                    float z1 = sum2(acc[rr * 8 + q * 2 + 1]) + sc.y + bb.y;
                    float g0 = 1.0f / (1.0f + expf(-z0));
                    float g1 = 1.0f / (1.0f + expf(-z1));
                    float2 rf = *(const float2*)(row + 128 + c0);
                    float2 st = *(const float2*)(srw + c0);
                    st.x += g0 * rf.x;
                    st.y += g1 * rf.y;
                    *(float2*)(srw + c0) = st;
                }
            }
        }
        __syncthreads();  // state visible to next pass's LN
    }

    // ---- store result ----
    {
        float4* og = (float4*)(out + rowBase * 128);
#pragma unroll
        for (int i = 0; i < 8; i++) {
            int idx = tid + i * NTHREADS;
            og[idx] = *(const float4*)&sS[(idx >> 5) * SSTR + (idx & 31) * 4];
        }
    }
}

extern "C" void kernel_launch(void* const* d_in, const int* in_sizes, int n_in,
                              void* d_out, int out_size) {
    const float* x    = (const float*)d_in[0];
    const float* ln_w = (const float*)d_in[1];
    const float* ln_b = (const float*)d_in[2];
    const float* w1   = (const float*)d_in[3];
    const float* b1   = (const float*)d_in[4];
    const float* w2   = (const float*)d_in[5];
    const float* b2   = (const float*)d_in[6];
    const float* wg   = (const float*)d_in[7];
    const float* bg   = (const float*)d_in[8];
    const int* passes = (const int*)d_in[9];
    float* out = (float*)d_out;

    pack_weights_kernel<<<192, 256>>>(w1, w2, wg);

    const int nrows = in_sizes[0] / 128;
    const int blocks = nrows / TM;

    cudaFuncSetAttribute(TinyRecurrentWorkshop_69054484185493_kernel,
                         cudaFuncAttributeMaxDynamicSharedMemorySize, SMEM_BYTES);
    TinyRecurrentWorkshop_69054484185493_kernel<<<blocks, NTHREADS, SMEM_BYTES>>>(
        x, ln_w, ln_b, b1, b2, bg, passes, out);
}

// round 9
// speedup vs baseline: 1.1112x; 1.0720x over previous
#include <cuda_runtime.h>
#include <cstdint>
#include <math.h>

#define NTHREADS 256
#define TM 64
#define SSTR 132                     /* 132 % 4 == 0, 132 % 32 == 4 */
#define ASTR 260                     /* 260 % 4 == 0, 260 % 32 == 4 */
#define TILE_F 4096                  /* 16 KB weight tile */

#define SA_OFF (TM * SSTR)           /* 8448  */
#define SW_OFF (SA_OFF + TM * ASTR)  /* 25088 */
#define SMEM_FLOATS (SW_OFF + 4 * TILE_F) /* 41472 */
#define SMEM_BYTES (SMEM_FLOATS * 4)      /* 165888 B */

typedef unsigned long long u64;

// k-pair-interleaved weights (constant; packed once per launch)
__device__ float W1P[128 * 256];
__device__ float W2P[256 * 128];
__device__ float WGP[256 * 128];

// ---------------- packed f32x2 (Blackwell FFMA2) ----------------
__device__ __forceinline__ u64 fma2(u64 a, u64 b, u64 c) {
    u64 d;
    asm("fma.rn.f32x2 %0, %1, %2, %3;" : "=l"(d) : "l"(a), "l"(b), "l"(c));
    return d;
}
__device__ __forceinline__ float sum2(u64 v) {
    float lo, hi;
    asm("mov.b64 {%0, %1}, %2;" : "=f"(lo), "=f"(hi) : "l"(v));
    return lo + hi;
}

// ---------------- cp.async ----------------
__device__ __forceinline__ void cp_async16(unsigned saddr, const void* g) {
    asm volatile("cp.async.ca.shared.global [%0], [%1], 16;" ::"r"(saddr), "l"(g));
}
__device__ __forceinline__ void cp_commit() {
    asm volatile("cp.async.commit_group;" ::: "memory");
}
__device__ __forceinline__ void cp_wait0() {
    asm volatile("cp.async.wait_group 0;" ::: "memory");
}
// half-scoped named barrier (128 threads)
__device__ __forceinline__ void barh(int bid) {
    asm volatile("bar.sync %0, 128;" ::"r"(bid) : "memory");
}
// one 16KB tile loaded by 128 threads (8 float4 each)
__device__ __forceinline__ void ldtile128(float* dst, const float* g, int htid) {
    unsigned s = (unsigned)__cvta_generic_to_shared(dst);
    const float4* g4 = (const float4*)g;
#pragma unroll
    for (int i = 0; i < 8; i++)
        cp_async16(s + (htid + i * 128) * 16, g4 + htid + i * 128);
    cp_commit();
}

__device__ __forceinline__ float gelu_f(float x) {
    return 0.5f * x * (1.0f + erff(x * 0.7071067811865476f));
}
__device__ __forceinline__ float sigmoid_f(float x) {
    return 1.0f / (1.0f + __expf(-x));
}

// ---------------- weight pre-pack: out[kp][n] = (in[2kp][n], in[2kp+1][n]) ---
__global__ void pack_weights_kernel(const float* __restrict__ w1,
                                    const float* __restrict__ w2,
                                    const float* __restrict__ wg) {
    int i = blockIdx.x * blockDim.x + threadIdx.x;  // 0 .. 49151
    int m = i >> 14;
    int r = i & 16383;
    if (m == 0) {
        int kp = r >> 8, n = r & 255;
        ((float2*)W1P)[r] = make_float2(w1[(2 * kp) * 256 + n], w1[(2 * kp + 1) * 256 + n]);
    } else if (m == 1) {
        int kp = r >> 7, n = r & 127;
        ((float2*)W2P)[r] = make_float2(w2[(2 * kp) * 128 + n], w2[(2 * kp + 1) * 128 + n]);
    } else {
        int kp = r >> 7, n = r & 127;
        ((float2*)WGP)[r] = make_float2(wg[(2 * kp) * 128 + n], wg[(2 * kp + 1) * 128 + n]);
    }
}

// ---------------- k-paired GEMM, warp-owned 8 rows x (Q*64) u64-cols ---------
// Q=4: N=256 (M1). Q=2: N=128 (M2/M3). Thread owns u64 cols q*64 + 2*lane,
// q = 0..Q-1, each col pair as one u64 acc of (even-k, odd-k) partials.
// A: SMEM rows (stride astr), LDS.128 broadcast per row per 4k.
// B: k-pair-packed weights in global, streamed via two 16KB half-owned buffers
// with half-scoped named barriers. ACCUMULATES into acc.
template <int Q, int NTILES>
__device__ __forceinline__ void gemm_h(const float* __restrict__ A0, int astr,
                                       const float* __restrict__ Bg,
                                       float* b0, float* b1, u64* acc,
                                       int lane, int bid, int htid) {
    constexpr int KQ = 16 / Q;  // kq (4k each) per tile
    ldtile128(b0, Bg, htid);
    cp_wait0();
    barh(bid);
    for (int t = 0; t < NTILES; t++) {
        if (t + 1 < NTILES)
            ldtile128(((t + 1) & 1) ? b1 : b0, Bg + (t + 1) * TILE_F, htid);
        const float* sB = (t & 1) ? b1 : b0;
        const float* At = A0 + t * (KQ * 4);
#pragma unroll
        for (int kq = 0; kq < KQ; kq++) {
            ulonglong2 a[8];
#pragma unroll
            for (int rr = 0; rr < 8; rr++)
                a[rr] = *(const ulonglong2*)(At + rr * astr + kq * 4);
#pragma unroll
            for (int j = 0; j < 2; j++) {
                const u64* bp = (const u64*)sB + (kq * 2 + j) * (Q * 64) + 2 * lane;
                u64 b[2 * Q];
#pragma unroll
                for (int q = 0; q < Q; q++)
                    *(ulonglong2*)&b[2 * q] = *(const ulonglong2*)(bp + q * 64);
#pragma unroll
                for (int rr = 0; rr < 8; rr++) {
                    u64 av = j ? a[rr].y : a[rr].x;
#pragma unroll
                    for (int c = 0; c < 2 * Q; c++)
                        acc[rr * 2 * Q + c] = fma2(av, b[c], acc[rr * 2 * Q + c]);
                }
            }
        }
        cp_wait0();
        barh(bid);
    }
}

// ---------------- main fused recurrent kernel ----------------
__global__ void __launch_bounds__(NTHREADS, 1)
TinyRecurrentWorkshop_69054484185493_kernel(
    const float* __restrict__ x,
    const float* __restrict__ ln_w, const float* __restrict__ ln_b,
    const float* __restrict__ b1, const float* __restrict__ b2,
    const float* __restrict__ bg,
    const int* __restrict__ passes_p,
    float* __restrict__ out) {
    extern __shared__ float smem[];
    float* sS = smem;            // state 64 x 132
    float* sA = smem + SA_OFF;   // h / act / refined : 64 x 260
    float* sW = smem + SW_OFF;   // 2 halves x 2 x 4096 weight buffers

    const int tid = threadIdx.x;
    const int w = tid >> 5, lane = tid & 31;
    const int half = tid >> 7, htid = tid & 127;
    const int bid = 1 + half;           // named barrier id per half
    const int wrow = w * 8;             // this warp's 8 rows (all phases)
    float* hb0 = sW + half * 2 * TILE_F;
    float* hb1 = hb0 + TILE_F;
    const long long rowBase = (long long)blockIdx.x * TM;

    // ---- load state tile (block-strided, one CTA sync) ----
    {
        const float4* xg = (const float4*)(x + rowBase * 128);
#pragma unroll
        for (int i = 0; i < 8; i++) {
            int idx = tid + i * NTHREADS;
            *(float4*)&sS[(idx >> 5) * SSTR + (idx & 31) * 4] = xg[idx];
        }
    }

    int npass = passes_p[0];
    if (npass < 1 || npass > 1024) {
        float f = __int_as_float(npass);
        npass = (int)f;
        if (npass < 1 || npass > 1024) npass = 8;
    }
    __syncthreads();

    const int r4 = lane >> 2;   // LN: 4 lanes per row, 8 rows per warp
    const int lq = lane & 3;

    for (int pass = 0; pass < npass; pass++) {
        // ---------- LayerNorm (warp-local): sS rows -> h in sA[:,0:128] ------
        {
            float4 xv[8];
            const float* sr = sS + (wrow + r4) * SSTR + lq * 32;
            float s = 0.f;
#pragma unroll
            for (int j = 0; j < 8; j++) {
                xv[j] = *(const float4*)(sr + j * 4);
                s += (xv[j].x + xv[j].y) + (xv[j].z + xv[j].w);
            }
            s += __shfl_xor_sync(0xFFFFFFFFu, s, 1);
            s += __shfl_xor_sync(0xFFFFFFFFu, s, 2);
            const float mu = s * (1.0f / 128.0f);
            float q = 0.f;
#pragma unroll
            for (int j = 0; j < 8; j++) {
                float d0 = xv[j].x - mu, d1 = xv[j].y - mu;
                float d2 = xv[j].z - mu, d3 = xv[j].w - mu;
                q += d0 * d0 + d1 * d1 + d2 * d2 + d3 * d3;
            }
            q += __shfl_xor_sync(0xFFFFFFFFu, q, 1);
            q += __shfl_xor_sync(0xFFFFFFFFu, q, 2);
            const float rstd = rsqrtf(q * (1.0f / 128.0f) + 1e-5f);
            float* hr = sA + (wrow + r4) * ASTR + lq * 32;
#pragma unroll
            for (int j = 0; j < 8; j++) {
                float4 wv = __ldg((const float4*)ln_w + lq * 8 + j);
                float4 bv = __ldg((const float4*)ln_b + lq * 8 + j);
                float4 h;
                h.x = (xv[j].x - mu) * rstd * wv.x + bv.x;
                h.y = (xv[j].y - mu) * rstd * wv.y + bv.y;
                h.z = (xv[j].z - mu) * rstd * wv.z + bv.z;
                h.w = (xv[j].w - mu) * rstd * wv.w + bv.w;
                *(float4*)(hr + j * 4) = h;
            }
        }
        __syncwarp();  // h visible warp-wide (A reads broadcast across lanes)

        // ---------- M1: g = h @ w1  (rows own, N=256, K=128) ----------
        u64 acc1[64];
#pragma unroll
        for (int i = 0; i < 64; i++) acc1[i] = 0ULL;
        gemm_h<4, 8>(sA + wrow * ASTR, ASTR, W1P, hb0, hb1, acc1, lane, bid, htid);

        // gelu(g + b1) -> sA rows own, cols 0..255
#pragma unroll
        for (int rr = 0; rr < 8; rr++) {
            float* ar = sA + (wrow + rr) * ASTR;
#pragma unroll
            for (int q = 0; q < 4; q++) {
                int c0 = q * 64 + 2 * lane;
                float2 bb = __ldg((const float2*)(b1 + c0));
                float2 o;
                o.x = gelu_f(sum2(acc1[rr * 8 + 2 * q + 0]) + bb.x);
                o.y = gelu_f(sum2(acc1[rr * 8 + 2 * q + 1]) + bb.y);
                *(float2*)(ar + c0) = o;
            }
        }
        __syncwarp();

        // ---------- M2: refined = act @ w2 + b2  (N=128, K=256) ----------
        u64 acc2[32];
#pragma unroll
        for (int i = 0; i < 32; i++) acc2[i] = 0ULL;
        gemm_h<2, 8>(sA + wrow * ASTR, ASTR, W2P, hb0, hb1, acc2, lane, bid, htid);

        float2 rf[16];  // refined values this thread owns
#pragma unroll
        for (int rr = 0; rr < 8; rr++) {
            float* ar = sA + (wrow + rr) * ASTR;
#pragma unroll
            for (int q = 0; q < 2; q++) {
                int c0 = q * 64 + 2 * lane;
                float2 bb = __ldg((const float2*)(b2 + c0));
                float2 v;
                v.x = sum2(acc2[rr * 4 + 2 * q + 0]) + bb.x;
                v.y = sum2(acc2[rr * 4 + 2 * q + 1]) + bb.y;
                rf[rr * 2 + q] = v;
                *(float2*)(ar + c0) = v;  // refined -> sA cols 0..127 (act dead)
            }
        }
        __syncwarp();

        // ---------- M3: z = state @ wg_s + refined @ wg_r (accumulated) ------
        u64 acc3[32];
#pragma unroll
        for (int i = 0; i < 32; i++) acc3[i] = 0ULL;
        gemm_h<2, 4>(sS + wrow * SSTR, SSTR, WGP, hb0, hb1, acc3, lane, bid, htid);
        gemm_h<2, 4>(sA + wrow * ASTR, ASTR, WGP + 16384, hb0, hb1, acc3, lane, bid, htid);

        // gate + residual update (same ownership -> warp-local)
#pragma unroll
        for (int rr = 0; rr < 8; rr++) {
            float* srw = sS + (wrow + rr) * SSTR;
#pragma unroll
            for (int q = 0; q < 2; q++) {
                int c0 = q * 64 + 2 * lane;
                float2 bb = __ldg((const float2*)(bg + c0));
                float g0 = sigmoid_f(sum2(acc3[rr * 4 + 2 * q + 0]) + bb.x);
                float g1 = sigmoid_f(sum2(acc3[rr * 4 + 2 * q + 1]) + bb.y);
                float2 st = *(const float2*)(srw + c0);
                st.x += g0 * rf[rr * 2 + q].x;
                st.y += g1 * rf[rr * 2 + q].y;
                *(float2*)(srw + c0) = st;
            }
        }
        __syncwarp();  // state visible warp-wide for next pass's LN
    }

    // ---- store result (block-strided; sync across warps once) ----
    __syncthreads();
    {
        float4* og = (float4*)(out + rowBase * 128);
#pragma unroll
        for (int i = 0; i < 8; i++) {
            int idx = tid + i * NTHREADS;
            og[idx] = *(const float4*)&sS[(idx >> 5) * SSTR + (idx & 31) * 4];
        }
    }
}

extern "C" void kernel_launch(void* const* d_in, const int* in_sizes, int n_in,
                              void* d_out, int out_size) {
    const float* x    = (const float*)d_in[0];
    const float* ln_w = (const float*)d_in[1];
    const float* ln_b = (const float*)d_in[2];
    const float* w1   = (const float*)d_in[3];
    const float* b1   = (const float*)d_in[4];
    const float* w2   = (const float*)d_in[5];
    const float* b2   = (const float*)d_in[6];
    const float* wg   = (const float*)d_in[7];
    const float* bg   = (const float*)d_in[8];
    const int* passes = (const int*)d_in[9];
    float* out = (float*)d_out;

    pack_weights_kernel<<<192, 256>>>(w1, w2, wg);

    const int nrows = in_sizes[0] / 128;
    const int blocks = nrows / TM;

    cudaFuncSetAttribute(TinyRecurrentWorkshop_69054484185493_kernel,
                         cudaFuncAttributeMaxDynamicSharedMemorySize, SMEM_BYTES);
    TinyRecurrentWorkshop_69054484185493_kernel<<<blocks, NTHREADS, SMEM_BYTES>>>(
        x, ln_w, ln_b, b1, b2, bg, passes, out);
}

// round 10
// speedup vs baseline: 1.1115x; 1.0002x over previous
#include <cuda_runtime.h>
#include <cstdint>
#include <math.h>

#define NTHREADS 256
#define TM 64
#define SSTR 132                     /* 132 % 4 == 0, 132 % 32 == 4 */
#define ASTR 260                     /* 260 % 4 == 0, 260 % 32 == 4 */
#define TILE_F 4096                  /* 16 KB weight tile */

#define SA_OFF (TM * SSTR)           /* 8448  */
#define SW_OFF (SA_OFF + TM * ASTR)  /* 25088 */
#define SMEM_FLOATS (SW_OFF + 4 * TILE_F) /* 41472 */
#define SMEM_BYTES (SMEM_FLOATS * 4)      /* 165888 B */

typedef unsigned long long u64;

// k-pair-interleaved weights (constant; packed once per launch)
__device__ float W1P[128 * 256];
__device__ float W2P[256 * 128];
__device__ float WGP[256 * 128];

// ---------------- packed f32x2 (Blackwell FFMA2) ----------------
__device__ __forceinline__ u64 fma2(u64 a, u64 b, u64 c) {
    u64 d;
    asm("fma.rn.f32x2 %0, %1, %2, %3;" : "=l"(d) : "l"(a), "l"(b), "l"(c));
    return d;
}
__device__ __forceinline__ float sum2(u64 v) {
    float lo, hi;
    asm("mov.b64 {%0, %1}, %2;" : "=f"(lo), "=f"(hi) : "l"(v));
    return lo + hi;
}

// ---------------- cp.async ----------------
__device__ __forceinline__ void cp_async16(unsigned saddr, const void* g) {
    asm volatile("cp.async.ca.shared.global [%0], [%1], 16;" ::"r"(saddr), "l"(g));
}
__device__ __forceinline__ void cp_commit() {
    asm volatile("cp.async.commit_group;" ::: "memory");
}
__device__ __forceinline__ void cp_wait0() {
    asm volatile("cp.async.wait_group 0;" ::: "memory");
}
// half-scoped named barrier (128 threads)
__device__ __forceinline__ void barh(int bid) {
    asm volatile("bar.sync %0, 128;" ::"r"(bid) : "memory");
}
// one 16KB tile loaded by 128 threads (8 float4 each)
__device__ __forceinline__ void ldtile128(float* dst, const float* g, int htid) {
    unsigned s = (unsigned)__cvta_generic_to_shared(dst);
    const float4* g4 = (const float4*)g;
#pragma unroll
    for (int i = 0; i < 8; i++)
        cp_async16(s + (htid + i * 128) * 16, g4 + htid + i * 128);
    cp_commit();
}

__device__ __forceinline__ float gelu_f(float x) {
    return 0.5f * x * (1.0f + erff(x * 0.7071067811865476f));
}
__device__ __forceinline__ float sigmoid_f(float x) {
    return 1.0f / (1.0f + __expf(-x));
}

// ---------------- weight pre-pack: out[kp][n] = (in[2kp][n], in[2kp+1][n]) ---
__global__ void pack_weights_kernel(const float* __restrict__ w1,
                                    const float* __restrict__ w2,
                                    const float* __restrict__ wg) {
    int i = blockIdx.x * blockDim.x + threadIdx.x;  // 0 .. 49151
    int m = i >> 14;
    int r = i & 16383;
    if (m == 0) {
        int kp = r >> 8, n = r & 255;
        ((float2*)W1P)[r] = make_float2(w1[(2 * kp) * 256 + n], w1[(2 * kp + 1) * 256 + n]);
    } else if (m == 1) {
        int kp = r >> 7, n = r & 127;
        ((float2*)W2P)[r] = make_float2(w2[(2 * kp) * 128 + n], w2[(2 * kp + 1) * 128 + n]);
    } else {
        int kp = r >> 7, n = r & 127;
        ((float2*)WGP)[r] = make_float2(wg[(2 * kp) * 128 + n], wg[(2 * kp + 1) * 128 + n]);
    }
}

// ---------------- k-paired GEMM, warp-owned 8 rows x (Q*64) u64-cols ---------
// Q=4: N=256 (M1). Q=2: N=128 (M2/M3). Thread owns u64 cols q*64 + 2*lane,
// q = 0..Q-1, each col pair as one u64 acc of (even-k, odd-k) partials.
// A: SMEM rows (stride astr), LDS.128 broadcast per row per 4k.
// B: k-pair-packed weights in global, streamed via two 16KB half-owned buffers
// with half-scoped named barriers. ACCUMULATES into acc.
template <int Q, int NTILES>
__device__ __forceinline__ void gemm_h(const float* __restrict__ A0, int astr,
                                       const float* __restrict__ Bg,
                                       float* b0, float* b1, u64* acc,
                                       int lane, int bid, int htid) {
    constexpr int KQ = 16 / Q;  // kq (4k each) per tile
    ldtile128(b0, Bg, htid);
    cp_wait0();
    barh(bid);
    for (int t = 0; t < NTILES; t++) {
        if (t + 1 < NTILES)
            ldtile128(((t + 1) & 1) ? b1 : b0, Bg + (t + 1) * TILE_F, htid);
        const float* sB = (t & 1) ? b1 : b0;
        const float* At = A0 + t * (KQ * 4);
#pragma unroll
        for (int kq = 0; kq < KQ; kq++) {
            ulonglong2 a[8];
#pragma unroll
            for (int rr = 0; rr < 8; rr++)
                a[rr] = *(const ulonglong2*)(At + rr * astr + kq * 4);
#pragma unroll
            for (int j = 0; j < 2; j++) {
                const u64* bp = (const u64*)sB + (kq * 2 + j) * (Q * 64) + 2 * lane;
                u64 b[2 * Q];
#pragma unroll
                for (int q = 0; q < Q; q++)
                    *(ulonglong2*)&b[2 * q] = *(const ulonglong2*)(bp + q * 64);
#pragma unroll
                for (int rr = 0; rr < 8; rr++) {
                    u64 av = j ? a[rr].y : a[rr].x;
#pragma unroll
                    for (int c = 0; c < 2 * Q; c++)
                        acc[rr * 2 * Q + c] = fma2(av, b[c], acc[rr * 2 * Q + c]);
                }
            }
        }
        cp_wait0();
        barh(bid);
    }
}

// ---------------- main fused recurrent kernel ----------------
__global__ void __launch_bounds__(NTHREADS, 1)
TinyRecurrentWorkshop_69054484185493_kernel(
    const float* __restrict__ x,
    const float* __restrict__ ln_w, const float* __restrict__ ln_b,
    const float* __restrict__ b1, const float* __restrict__ b2,
    const float* __restrict__ bg,
    const int* __restrict__ passes_p,
    float* __restrict__ out) {
    extern __shared__ float smem[];
    float* sS = smem;            // state 64 x 132
    float* sA = smem + SA_OFF;   // h / act / refined : 64 x 260
    float* sW = smem + SW_OFF;   // 2 halves x 2 x 4096 weight buffers

    const int tid = threadIdx.x;
    const int w = tid >> 5, lane = tid & 31;
    const int half = tid >> 7, htid = tid & 127;
    const int bid = 1 + half;           // named barrier id per half
    const int wrow = w * 8;             // this warp's 8 rows (all phases)
    float* hb0 = sW + half * 2 * TILE_F;
    float* hb1 = hb0 + TILE_F;
    const long long rowBase = (long long)blockIdx.x * TM;

    // ---- load state tile (block-strided, one CTA sync) ----
    {
        const float4* xg = (const float4*)(x + rowBase * 128);
#pragma unroll
        for (int i = 0; i < 8; i++) {
            int idx = tid + i * NTHREADS;
            *(float4*)&sS[(idx >> 5) * SSTR + (idx & 31) * 4] = xg[idx];
        }
    }

    int npass = passes_p[0];
    if (npass < 1 || npass > 1024) {
        float f = __int_as_float(npass);
        npass = (int)f;
        if (npass < 1 || npass > 1024) npass = 8;
    }
    __syncthreads();

    const int r4 = lane >> 2;   // LN: 4 lanes per row, 8 rows per warp
    const int lq = lane & 3;

    for (int pass = 0; pass < npass; pass++) {
        // ---------- LayerNorm (warp-local): sS rows -> h in sA[:,0:128] ------
        {
            float4 xv[8];
            const float* sr = sS + (wrow + r4) * SSTR + lq * 32;
            float s = 0.f;
#pragma unroll
            for (int j = 0; j < 8; j++) {
                xv[j] = *(const float4*)(sr + j * 4);
                s += (xv[j].x + xv[j].y) + (xv[j].z + xv[j].w);
            }
            s += __shfl_xor_sync(0xFFFFFFFFu, s, 1);
            s += __shfl_xor_sync(0xFFFFFFFFu, s, 2);
            const float mu = s * (1.0f / 128.0f);
            float q = 0.f;
#pragma unroll
            for (int j = 0; j < 8; j++) {
                float d0 = xv[j].x - mu, d1 = xv[j].y - mu;
                float d2 = xv[j].z - mu, d3 = xv[j].w - mu;
                q += d0 * d0 + d1 * d1 + d2 * d2 + d3 * d3;
            }
            q += __shfl_xor_sync(0xFFFFFFFFu, q, 1);
            q += __shfl_xor_sync(0xFFFFFFFFu, q, 2);
            const float rstd = rsqrtf(q * (1.0f / 128.0f) + 1e-5f);
            float* hr = sA + (wrow + r4) * ASTR + lq * 32;
#pragma unroll
            for (int j = 0; j < 8; j++) {
                float4 wv = __ldg((const float4*)ln_w + lq * 8 + j);
                float4 bv = __ldg((const float4*)ln_b + lq * 8 + j);
                float4 h;
                h.x = (xv[j].x - mu) * rstd * wv.x + bv.x;
                h.y = (xv[j].y - mu) * rstd * wv.y + bv.y;
                h.z = (xv[j].z - mu) * rstd * wv.z + bv.z;
                h.w = (xv[j].w - mu) * rstd * wv.w + bv.w;
                *(float4*)(hr + j * 4) = h;
            }
        }
        __syncwarp();  // h visible warp-wide (A reads broadcast across lanes)

        // ---------- M1: g = h @ w1  (rows own, N=256, K=128) ----------
        u64 acc1[64];
#pragma unroll
        for (int i = 0; i < 64; i++) acc1[i] = 0ULL;
        gemm_h<4, 8>(sA + wrow * ASTR, ASTR, W1P, hb0, hb1, acc1, lane, bid, htid);

        // gelu(g + b1) -> sA rows own, cols 0..255
#pragma unroll
        for (int rr = 0; rr < 8; rr++) {
            float* ar = sA + (wrow + rr) * ASTR;
#pragma unroll
            for (int q = 0; q < 4; q++) {
                int c0 = q * 64 + 2 * lane;
                float2 bb = __ldg((const float2*)(b1 + c0));
                float2 o;
                o.x = gelu_f(sum2(acc1[rr * 8 + 2 * q + 0]) + bb.x);
                o.y = gelu_f(sum2(acc1[rr * 8 + 2 * q + 1]) + bb.y);
                *(float2*)(ar + c0) = o;
            }
        }
        __syncwarp();

        // ---------- M2: refined = act @ w2 + b2  (N=128, K=256) ----------
        u64 acc2[32];
#pragma unroll
        for (int i = 0; i < 32; i++) acc2[i] = 0ULL;
        gemm_h<2, 8>(sA + wrow * ASTR, ASTR, W2P, hb0, hb1, acc2, lane, bid, htid);

        float2 rf[16];  // refined values this thread owns
#pragma unroll
        for (int rr = 0; rr < 8; rr++) {
            float* ar = sA + (wrow + rr) * ASTR;
#pragma unroll
            for (int q = 0; q < 2; q++) {
                int c0 = q * 64 + 2 * lane;
                float2 bb = __ldg((const float2*)(b2 + c0));
                float2 v;
                v.x = sum2(acc2[rr * 4 + 2 * q + 0]) + bb.x;
                v.y = sum2(acc2[rr * 4 + 2 * q + 1]) + bb.y;
                rf[rr * 2 + q] = v;
                *(float2*)(ar + c0) = v;  // refined -> sA cols 0..127 (act dead)
            }
        }
        __syncwarp();

        // ---------- M3: z = state @ wg_s + refined @ wg_r (accumulated) ------
        u64 acc3[32];
#pragma unroll
        for (int i = 0; i < 32; i++) acc3[i] = 0ULL;
        gemm_h<2, 4>(sS + wrow * SSTR, SSTR, WGP, hb0, hb1, acc3, lane, bid, htid);
        gemm_h<2, 4>(sA + wrow * ASTR, ASTR, WGP + 16384, hb0, hb1, acc3, lane, bid, htid);

        // gate + residual update (same ownership -> warp-local)
#pragma unroll
        for (int rr = 0; rr < 8; rr++) {
            float* srw = sS + (wrow + rr) * SSTR;
#pragma unroll
            for (int q = 0; q < 2; q++) {
                int c0 = q * 64 + 2 * lane;
                float2 bb = __ldg((const float2*)(bg + c0));
                float g0 = sigmoid_f(sum2(acc3[rr * 4 + 2 * q + 0]) + bb.x);
                float g1 = sigmoid_f(sum2(acc3[rr * 4 + 2 * q + 1]) + bb.y);
                float2 st = *(const float2*)(srw + c0);
                st.x += g0 * rf[rr * 2 + q].x;
                st.y += g1 * rf[rr * 2 + q].y;
                *(float2*)(srw + c0) = st;
            }
        }
        __syncwarp();  // state visible warp-wide for next pass's LN
    }

    // ---- store result (block-strided; sync across warps once) ----
    __syncthreads();
    {
        float4* og = (float4*)(out + rowBase * 128);
#pragma unroll
        for (int i = 0; i < 8; i++) {
            int idx = tid + i * NTHREADS;
            og[idx] = *(const float4*)&sS[(idx >> 5) * SSTR + (idx & 31) * 4];
        }
    }
}

extern "C" void kernel_launch(void* const* d_in, const int* in_sizes, int n_in,
                              void* d_out, int out_size) {
    const float* x    = (const float*)d_in[0];
    const float* ln_w = (const float*)d_in[1];
    const float* ln_b = (const float*)d_in[2];
    const float* w1   = (const float*)d_in[3];
    const float* b1   = (const float*)d_in[4];
    const float* w2   = (const float*)d_in[5];
    const float* b2   = (const float*)d_in[6];
    const float* wg   = (const float*)d_in[7];
    const float* bg   = (const float*)d_in[8];
    const int* passes = (const int*)d_in[9];
    float* out = (float*)d_out;

    pack_weights_kernel<<<192, 256>>>(w1, w2, wg);

    const int nrows = in_sizes[0] / 128;
    const int blocks = nrows / TM;

    cudaFuncSetAttribute(TinyRecurrentWorkshop_69054484185493_kernel,
                         cudaFuncAttributeMaxDynamicSharedMemorySize, SMEM_BYTES);
    TinyRecurrentWorkshop_69054484185493_kernel<<<blocks, NTHREADS, SMEM_BYTES>>>(
        x, ln_w, ln_b, b1, b2, bg, passes, out);
}

// round 11
// speedup vs baseline: 1.1121x; 1.0006x over previous
#include <cuda_runtime.h>
#include <cstdint>
#include <math.h>

#define NTHREADS 256
#define TM 64
#define SSTR 132                     /* 132 % 4 == 0, 132 % 32 == 4 */
#define ASTR 260                     /* 260 % 4 == 0, 260 % 32 == 4 */
#define TILE_F 4096                  /* 16 KB weight tile */

#define SA_OFF (TM * SSTR)           /* 8448  */
#define SW_OFF (SA_OFF + TM * ASTR)  /* 25088 */
#define SMEM_FLOATS (SW_OFF + 4 * TILE_F) /* 41472 */
#define SMEM_BYTES (SMEM_FLOATS * 4)      /* 165888 B */

typedef unsigned long long u64;

// k-pair-interleaved weights (constant; packed once per launch)
__device__ float W1P[128 * 256];
__device__ float W2P[256 * 128];
__device__ float WGP[256 * 128];

// ---------------- packed f32x2 (Blackwell FFMA2) ----------------
__device__ __forceinline__ u64 fma2(u64 a, u64 b, u64 c) {
    u64 d;
    asm("fma.rn.f32x2 %0, %1, %2, %3;" : "=l"(d) : "l"(a), "l"(b), "l"(c));
    return d;
}
__device__ __forceinline__ float sum2(u64 v) {
    float lo, hi;
    asm("mov.b64 {%0, %1}, %2;" : "=f"(lo), "=f"(hi) : "l"(v));
    return lo + hi;
}

// ---------------- cp.async ----------------
__device__ __forceinline__ void cp_async16(unsigned saddr, const void* g) {
    asm volatile("cp.async.ca.shared.global [%0], [%1], 16;" ::"r"(saddr), "l"(g));
}
__device__ __forceinline__ void cp_commit() {
    asm volatile("cp.async.commit_group;" ::: "memory");
}
__device__ __forceinline__ void cp_wait0() {
    asm volatile("cp.async.wait_group 0;" ::: "memory");
}
// half-scoped named barrier (128 threads)
__device__ __forceinline__ void barh(int bid) {
    asm volatile("bar.sync %0, 128;" ::"r"(bid) : "memory");
}
// one 16KB tile loaded by 128 threads (8 float4 each)
__device__ __forceinline__ void ldtile128(float* dst, const float* g, int htid) {
    unsigned s = (unsigned)__cvta_generic_to_shared(dst);
    const float4* g4 = (const float4*)g;
#pragma unroll
    for (int i = 0; i < 8; i++)
        cp_async16(s + (htid + i * 128) * 16, g4 + htid + i * 128);
    cp_commit();
}

__device__ __forceinline__ float gelu_f(float x) {
    return 0.5f * x * (1.0f + erff(x * 0.7071067811865476f));
}
__device__ __forceinline__ float sigmoid_f(float x) {
    return 1.0f / (1.0f + __expf(-x));
}

// ---------------- weight pre-pack: out[kp][n] = (in[2kp][n], in[2kp+1][n]) ---
__global__ void pack_weights_kernel(const float* __restrict__ w1,
                                    const float* __restrict__ w2,
                                    const float* __restrict__ wg) {
    int i = blockIdx.x * blockDim.x + threadIdx.x;  // 0 .. 49151
    int m = i >> 14;
    int r = i & 16383;
    if (m == 0) {
        int kp = r >> 8, n = r & 255;
        ((float2*)W1P)[r] = make_float2(w1[(2 * kp) * 256 + n], w1[(2 * kp + 1) * 256 + n]);
    } else if (m == 1) {
        int kp = r >> 7, n = r & 127;
        ((float2*)W2P)[r] = make_float2(w2[(2 * kp) * 128 + n], w2[(2 * kp + 1) * 128 + n]);
    } else {
        int kp = r >> 7, n = r & 127;
        ((float2*)WGP)[r] = make_float2(wg[(2 * kp) * 128 + n], wg[(2 * kp + 1) * 128 + n]);
    }
}

// ---------------- k-paired GEMM, warp-owned 8 rows x (Q*64) u64-cols ---------
// Q=4: N=256 (M1). Q=2: N=128 (M2/M3). Thread owns u64 cols q*64 + 2*lane,
// q = 0..Q-1, each col pair as one u64 acc of (even-k, odd-k) partials.
// A: SMEM rows (stride astr), LDS.128 broadcast per row per 4k.
// B: k-pair-packed weights in global, streamed via two 16KB half-owned buffers
// with half-scoped named barriers. ACCUMULATES into acc.
template <int Q, int NTILES>
__device__ __forceinline__ void gemm_h(const float* __restrict__ A0, int astr,
                                       const float* __restrict__ Bg,
                                       float* b0, float* b1, u64* acc,
                                       int lane, int bid, int htid) {
    constexpr int KQ = 16 / Q;  // kq (4k each) per tile
    ldtile128(b0, Bg, htid);
    cp_wait0();
    barh(bid);
    for (int t = 0; t < NTILES; t++) {
        if (t + 1 < NTILES)
            ldtile128(((t + 1) & 1) ? b1 : b0, Bg + (t + 1) * TILE_F, htid);
        const float* sB = (t & 1) ? b1 : b0;
        const float* At = A0 + t * (KQ * 4);
#pragma unroll
        for (int kq = 0; kq < KQ; kq++) {
            ulonglong2 a[8];
#pragma unroll
            for (int rr = 0; rr < 8; rr++)
                a[rr] = *(const ulonglong2*)(At + rr * astr + kq * 4);
#pragma unroll
            for (int j = 0; j < 2; j++) {
                const u64* bp = (const u64*)sB + (kq * 2 + j) * (Q * 64) + 2 * lane;
                u64 b[2 * Q];
#pragma unroll
                for (int q = 0; q < Q; q++)
                    *(ulonglong2*)&b[2 * q] = *(const ulonglong2*)(bp + q * 64);
#pragma unroll
                for (int rr = 0; rr < 8; rr++) {
                    u64 av = j ? a[rr].y : a[rr].x;
#pragma unroll
                    for (int c = 0; c < 2 * Q; c++)
                        acc[rr * 2 * Q + c] = fma2(av, b[c], acc[rr * 2 * Q + c]);
                }
            }
        }
        cp_wait0();
        barh(bid);
    }
}

// ---------------- main fused recurrent kernel ----------------
__global__ void __launch_bounds__(NTHREADS, 1)
TinyRecurrentWorkshop_69054484185493_kernel(
    const float* __restrict__ x,
    const float* __restrict__ ln_w, const float* __restrict__ ln_b,
    const float* __restrict__ b1, const float* __restrict__ b2,
    const float* __restrict__ bg,
    const int* __restrict__ passes_p,
    float* __restrict__ out) {
    extern __shared__ float smem[];
    float* sS = smem;            // state 64 x 132
    float* sA = smem + SA_OFF;   // h / act / refined : 64 x 260
    float* sW = smem + SW_OFF;   // 2 halves x 2 x 4096 weight buffers

    const int tid = threadIdx.x;
    const int w = tid >> 5, lane = tid & 31;
    const int half = tid >> 7, htid = tid & 127;
    const int bid = 1 + half;           // named barrier id per half
    const int wrow = w * 8;             // this warp's 8 rows (all phases)
    float* hb0 = sW + half * 2 * TILE_F;
    float* hb1 = hb0 + TILE_F;
    const long long rowBase = (long long)blockIdx.x * TM;

    // ---- load state tile (block-strided, one CTA sync) ----
    {
        const float4* xg = (const float4*)(x + rowBase * 128);
#pragma unroll
        for (int i = 0; i < 8; i++) {
            int idx = tid + i * NTHREADS;
            *(float4*)&sS[(idx >> 5) * SSTR + (idx & 31) * 4] = xg[idx];
        }
    }

    int npass = passes_p[0];
    if (npass < 1 || npass > 1024) {
        float f = __int_as_float(npass);
        npass = (int)f;
        if (npass < 1 || npass > 1024) npass = 8;
    }
    __syncthreads();

    const int r4 = lane >> 2;   // LN: 4 lanes per row, 8 rows per warp
    const int lq = lane & 3;

    for (int pass = 0; pass < npass; pass++) {
        // ---------- LayerNorm (warp-local): sS rows -> h in sA[:,0:128] ------
        {
            float4 xv[8];
            const float* sr = sS + (wrow + r4) * SSTR + lq * 32;
            float s = 0.f;
#pragma unroll
            for (int j = 0; j < 8; j++) {
                xv[j] = *(const float4*)(sr + j * 4);
                s += (xv[j].x + xv[j].y) + (xv[j].z + xv[j].w);
            }
            s += __shfl_xor_sync(0xFFFFFFFFu, s, 1);
            s += __shfl_xor_sync(0xFFFFFFFFu, s, 2);
            const float mu = s * (1.0f / 128.0f);
            float q = 0.f;
#pragma unroll
            for (int j = 0; j < 8; j++) {
                float d0 = xv[j].x - mu, d1 = xv[j].y - mu;
                float d2 = xv[j].z - mu, d3 = xv[j].w - mu;
                q += d0 * d0 + d1 * d1 + d2 * d2 + d3 * d3;
            }
            q += __shfl_xor_sync(0xFFFFFFFFu, q, 1);
            q += __shfl_xor_sync(0xFFFFFFFFu, q, 2);
            const float rstd = rsqrtf(q * (1.0f / 128.0f) + 1e-5f);
            float* hr = sA + (wrow + r4) * ASTR + lq * 32;
#pragma unroll
            for (int j = 0; j < 8; j++) {
                float4 wv = __ldg((const float4*)ln_w + lq * 8 + j);
                float4 bv = __ldg((const float4*)ln_b + lq * 8 + j);
                float4 h;
                h.x = (xv[j].x - mu) * rstd * wv.x + bv.x;
                h.y = (xv[j].y - mu) * rstd * wv.y + bv.y;
                h.z = (xv[j].z - mu) * rstd * wv.z + bv.z;
                h.w = (xv[j].w - mu) * rstd * wv.w + bv.w;
                *(float4*)(hr + j * 4) = h;
            }
        }
        __syncwarp();  // h visible warp-wide (A reads broadcast across lanes)

        // ---------- M1: g = h @ w1  (rows own, N=256, K=128) ----------
        u64 acc1[64];
#pragma unroll
        for (int i = 0; i < 64; i++) acc1[i] = 0ULL;
        gemm_h<4, 8>(sA + wrow * ASTR, ASTR, W1P, hb0, hb1, acc1, lane, bid, htid);

        // gelu(g + b1) -> sA rows own, cols 0..255
#pragma unroll
        for (int rr = 0; rr < 8; rr++) {
            float* ar = sA + (wrow + rr) * ASTR;
#pragma unroll
            for (int q = 0; q < 4; q++) {
                int c0 = q * 64 + 2 * lane;
                float2 bb = __ldg((const float2*)(b1 + c0));
                float2 o;
                o.x = gelu_f(sum2(acc1[rr * 8 + 2 * q + 0]) + bb.x);
                o.y = gelu_f(sum2(acc1[rr * 8 + 2 * q + 1]) + bb.y);
                *(float2*)(ar + c0) = o;
            }
        }
        __syncwarp();

        // ---------- M2: refined = act @ w2 + b2  (N=128, K=256) ----------
        u64 acc2[32];
#pragma unroll
        for (int i = 0; i < 32; i++) acc2[i] = 0ULL;
        gemm_h<2, 8>(sA + wrow * ASTR, ASTR, W2P, hb0, hb1, acc2, lane, bid, htid);

        float2 rf[16];  // refined values this thread owns
#pragma unroll
        for (int rr = 0; rr < 8; rr++) {
            float* ar = sA + (wrow + rr) * ASTR;
#pragma unroll
            for (int q = 0; q < 2; q++) {
                int c0 = q * 64 + 2 * lane;
                float2 bb = __ldg((const float2*)(b2 + c0));
                float2 v;
                v.x = sum2(acc2[rr * 4 + 2 * q + 0]) + bb.x;
                v.y = sum2(acc2[rr * 4 + 2 * q + 1]) + bb.y;
                rf[rr * 2 + q] = v;
                *(float2*)(ar + c0) = v;  // refined -> sA cols 0..127 (act dead)
            }
        }
        __syncwarp();

        // ---------- M3: z = state @ wg_s + refined @ wg_r (accumulated) ------
        u64 acc3[32];
#pragma unroll
        for (int i = 0; i < 32; i++) acc3[i] = 0ULL;
        gemm_h<2, 4>(sS + wrow * SSTR, SSTR, WGP, hb0, hb1, acc3, lane, bid, htid);
        gemm_h<2, 4>(sA + wrow * ASTR, ASTR, WGP + 16384, hb0, hb1, acc3, lane, bid, htid);

        // gate + residual update (same ownership -> warp-local)
#pragma unroll
        for (int rr = 0; rr < 8; rr++) {
            float* srw = sS + (wrow + rr) * SSTR;
#pragma unroll
            for (int q = 0; q < 2; q++) {
                int c0 = q * 64 + 2 * lane;
                float2 bb = __ldg((const float2*)(bg + c0));
                float g0 = sigmoid_f(sum2(acc3[rr * 4 + 2 * q + 0]) + bb.x);
                float g1 = sigmoid_f(sum2(acc3[rr * 4 + 2 * q + 1]) + bb.y);
                float2 st = *(const float2*)(srw + c0);
                st.x += g0 * rf[rr * 2 + q].x;
                st.y += g1 * rf[rr * 2 + q].y;
                *(float2*)(srw + c0) = st;
            }
        }
        __syncwarp();  // state visible warp-wide for next pass's LN
    }

    // ---- store result (block-strided; sync across warps once) ----
    __syncthreads();
    {
        float4* og = (float4*)(out + rowBase * 128);
#pragma unroll
        for (int i = 0; i < 8; i++) {
            int idx = tid + i * NTHREADS;
            og[idx] = *(const float4*)&sS[(idx >> 5) * SSTR + (idx & 31) * 4];
        }
    }
}

extern "C" void kernel_launch(void* const* d_in, const int* in_sizes, int n_in,
                              void* d_out, int out_size) {
    const float* x    = (const float*)d_in[0];
    const float* ln_w = (const float*)d_in[1];
    const float* ln_b = (const float*)d_in[2];
    const float* w1   = (const float*)d_in[3];
    const float* b1   = (const float*)d_in[4];
    const float* w2   = (const float*)d_in[5];
    const float* b2   = (const float*)d_in[6];
    const float* wg   = (const float*)d_in[7];
    const float* bg   = (const float*)d_in[8];
    const int* passes = (const int*)d_in[9];
    float* out = (float*)d_out;

    pack_weights_kernel<<<192, 256>>>(w1, w2, wg);

    const int nrows = in_sizes[0] / 128;
    const int blocks = nrows / TM;

    cudaFuncSetAttribute(TinyRecurrentWorkshop_69054484185493_kernel,
                         cudaFuncAttributeMaxDynamicSharedMemorySize, SMEM_BYTES);
    TinyRecurrentWorkshop_69054484185493_kernel<<<blocks, NTHREADS, SMEM_BYTES>>>(
        x, ln_w, ln_b, b1, b2, bg, passes, out);
}